// round 3
// baseline (speedup 1.0000x reference)
#include <cuda_runtime.h>
#include <cstdint>
#include <math.h>

#define BTOK 4096
#define DIM 1024
#define HID 4096
#define NE 8
#define NSLOT (BTOK*2)
#define CAP 9216
#define MTILES (CAP/128)      // 72

// ---------------- scratch (device globals; no runtime allocation) ----------------
__device__ __align__(128) float g_xn[BTOK*DIM];            // pooled -> layernormed (tf32 RNA)
__device__ __align__(128) float g_hid[(size_t)CAP*HID];    // silu(hidden), tf32 RNA
__device__ __align__(128) float g_y[(size_t)CAP*DIM];      // expert outputs
__device__ int   g_tok[CAP];
__device__ int   g_slot[NSLOT];
__device__ float g_topw[NSLOT];
__device__ int   g_topi[NSLOT];
__device__ int   g_cnt[NE];
__device__ int   g_cur[NE];
__device__ int   g_off[NE+1];
__device__ int   g_tile_e[MTILES];

// ---------------- helpers ----------------
__device__ __forceinline__ uint32_t cvt_tf32(float x){
    uint32_t u; asm("cvt.rna.tf32.f32 %0, %1;" : "=r"(u) : "f"(x)); return u;
}
__device__ __forceinline__ void cp16(uint32_t dst, const void* src){
    asm volatile("cp.async.cg.shared.global [%0], [%1], 16;\n" :: "r"(dst), "l"(src));
}
__device__ __forceinline__ void mma_tf32(float* c, const uint32_t* a, const uint32_t* b){
    asm volatile("mma.sync.aligned.m16n8k8.row.col.f32.tf32.tf32.f32 "
        "{%0,%1,%2,%3}, {%4,%5,%6,%7}, {%8,%9}, {%0,%1,%2,%3};"
        : "+f"(c[0]), "+f"(c[1]), "+f"(c[2]), "+f"(c[3])
        : "r"(a[0]), "r"(a[1]), "r"(a[2]), "r"(a[3]), "r"(b[0]), "r"(b[1]));
}
// swizzled float index inside a [row][32-float] smem tile: conflict-free for mma frag reads
__device__ __forceinline__ int swzf(int r, int c){
    return r*32 + ((((c>>2) ^ (r & 7)) << 2) | (c & 3));
}

// ---------------- small kernels ----------------
__global__ void init_k(){
    int t = blockIdx.x*blockDim.x + threadIdx.x;
    if (t < NE){ g_cnt[t]=0; g_cur[t]=0; }
    if (t < MTILES) g_tile_e[t] = -1;
    if (t < CAP) g_tok[t] = 0;
}

// warp per (b,d) row of 64 spatial floats — coalesced float2 lane loads
__global__ void pool_k(const float* __restrict__ x){
    int g = blockIdx.x*blockDim.x + threadIdx.x;
    int row = g >> 5, lane = g & 31;
    float2 v = ((const float2*)(x + (size_t)row*64))[lane];
    float s = v.x + v.y;
#pragma unroll
    for (int o=16;o;o>>=1) s += __shfl_xor_sync(0xffffffffu, s, o);
    if (!lane) g_xn[row] = s * (1.0f/64.0f);
}

__global__ void __launch_bounds__(256) lngate_k(const float* __restrict__ gamma,
                                                const float* __restrict__ beta,
                                                const float* __restrict__ wg,
                                                const float* __restrict__ bg){
    const int b = blockIdx.x, t = threadIdx.x;
    __shared__ float srow[DIM];
    __shared__ float rs[8], rss[8], slog[8];
    float4 v = ((const float4*)(g_xn + (size_t)b*DIM))[t];
    float s  = (v.x+v.y)+(v.z+v.w);
    float ss = (v.x*v.x+v.y*v.y)+(v.z*v.z+v.w*v.w);
#pragma unroll
    for (int o=16;o;o>>=1){ s += __shfl_xor_sync(0xffffffffu, s, o); ss += __shfl_xor_sync(0xffffffffu, ss, o); }
    const int lane = t & 31, w = t >> 5;
    if (!lane){ rs[w]=s; rss[w]=ss; }
    __syncthreads();
    float tot=0.f, tot2=0.f;
#pragma unroll
    for (int i=0;i<8;i++){ tot += rs[i]; tot2 += rss[i]; }
    const float mean = tot * (1.0f/DIM);
    const float var  = tot2 * (1.0f/DIM) - mean*mean;
    const float rinv = rsqrtf(var + 1e-5f);
    float4 g4 = ((const float4*)gamma)[t];
    float4 be4 = ((const float4*)beta)[t];
    float4 xn;
    xn.x = (v.x-mean)*rinv*g4.x + be4.x;
    xn.y = (v.y-mean)*rinv*g4.y + be4.y;
    xn.z = (v.z-mean)*rinv*g4.z + be4.z;
    xn.w = (v.w-mean)*rinv*g4.w + be4.w;
    ((float4*)srow)[t] = xn;                 // full precision for gating
    float4 xr;
    xr.x = __uint_as_float(cvt_tf32(xn.x));
    xr.y = __uint_as_float(cvt_tf32(xn.y));
    xr.z = __uint_as_float(cvt_tf32(xn.z));
    xr.w = __uint_as_float(cvt_tf32(xn.w));
    ((float4*)(g_xn + (size_t)b*DIM))[t] = xr;   // tf32-rounded for GEMM
    __syncthreads();
    const float4* wrow = (const float4*)(wg + (size_t)w*DIM);
    const float4* sr = (const float4*)srow;
    float acc = 0.f;
#pragma unroll
    for (int i=0;i<8;i++){
        int idx = lane + i*32;
        float4 a = sr[idx], ww = wrow[idx];
        acc += a.x*ww.x + a.y*ww.y + a.z*ww.z + a.w*ww.w;
    }
#pragma unroll
    for (int o=16;o;o>>=1) acc += __shfl_xor_sync(0xffffffffu, acc, o);
    if (!lane) slog[w] = acc + bg[w];
    __syncthreads();
    if (!t){
        int e0 = 0;
#pragma unroll
        for (int i=1;i<8;i++) if (slog[i] > slog[e0]) e0 = i;
        int e1 = (e0==0) ? 1 : 0;
#pragma unroll
        for (int i=0;i<8;i++) if (i!=e0 && slog[i] > slog[e1]) e1 = i;
        float z = expf(slog[e1] - slog[e0]);      // v1 <= v0
        g_topi[b*2]=e0; g_topi[b*2+1]=e1;
        g_topw[b*2]=1.0f/(1.0f+z); g_topw[b*2+1]=z/(1.0f+z);
        atomicAdd(&g_cnt[e0],1); atomicAdd(&g_cnt[e1],1);
    }
}

__global__ void scan_k(){
    if (threadIdx.x==0 && blockIdx.x==0){
        int off = 0;
        for (int e=0;e<NE;e++){
            g_off[e] = off;
            int nt = (g_cnt[e] + 127) >> 7;
            int t0 = off >> 7;
            for (int i=0;i<nt;i++) g_tile_e[t0+i] = e;
            off += nt << 7;
        }
        g_off[NE] = off;
    }
}

__global__ void scatter_k(){
    int i = blockIdx.x*blockDim.x + threadIdx.x;
    if (i >= NSLOT) return;
    int e = g_topi[i];
    int p = g_off[e] + atomicAdd(&g_cur[e], 1);
    g_tok[p] = i >> 1;
    g_slot[i] = p;
}

// ---------------- 3-stage pipelined tf32 mma GEMM ----------------
// C[mtile*128+m, ntile*128+n] = A[m,:] . W[e, n, :]   (both K-major)
// smem: 3 stages x (A 128x32 + B 128x32 floats) = 3 x 32KB = 96KB
template<int KD, int ND, bool GATHER, bool SILU>
__global__ void __launch_bounds__(256,2) gemm_k(const float* __restrict__ W,
                                                const float* __restrict__ bias){
    extern __shared__ float smf[];
    const int ntile = blockIdx.x, mtile = blockIdx.y;
    const int e = g_tile_e[mtile];
    if (e < 0) return;
    const int t = threadIdx.x;
    const int arow = t >> 1;           // 0..127
    const int af   = (t & 1) * 4;      // float4 slot base within 32-float chunk

    const float* aptr;
    if (GATHER) aptr = g_xn  + (size_t)g_tok[mtile*128 + arow]*KD;
    else        aptr = g_hid + (size_t)(mtile*128 + arow)*KD;
    const float* bptr = W + (size_t)e*ND*KD + (size_t)(ntile*128 + arow)*KD;
    const float* bias_e = bias + (size_t)e*ND;

    uint32_t sAu = (uint32_t)__cvta_generic_to_shared(smf);
    int dstoff[4];
#pragma unroll
    for (int i=0;i<4;i++){
        int f = af + i;
        dstoff[i] = arow*32 + ((f ^ (arow & 7)) << 2);   // floats
    }

    const int NK = KD/32;
    // prologue: stages 0,1
#pragma unroll
    for (int c=0;c<2;c++){
#pragma unroll
        for (int i=0;i<4;i++){
            cp16(sAu + (uint32_t)(c*8192 + dstoff[i])*4u,        aptr + c*32 + (af+i)*4);
            cp16(sAu + (uint32_t)(c*8192 + 4096 + dstoff[i])*4u, bptr + c*32 + (af+i)*4);
        }
        asm volatile("cp.async.commit_group;\n");
    }

    const int w = t>>5, lane = t&31;
    const int wm = w & 1, wn = w >> 1;        // 2 x 4 warp grid; warp tile 64x32
    const int lr = lane >> 2, lc = lane & 3;
    float acc[4][4][4];
#pragma unroll
    for (int a=0;a<4;a++)
#pragma unroll
        for (int bb=0;bb<4;bb++)
#pragma unroll
            for (int c=0;c<4;c++) acc[a][bb][c] = 0.f;

    int buf = 0, nbuf = 2;
    for (int kc=0; kc<NK; kc++){
        asm volatile("cp.async.wait_group 1;\n");
        __syncthreads();
        // prefetch stage kc+2 into buffer nbuf (its prior contents were computed
        // at kc-1, completion guaranteed by the sync above)
        if (kc+2 < NK){
            const float* as = aptr + (kc+2)*32;
            const float* bs = bptr + (kc+2)*32;
#pragma unroll
            for (int i=0;i<4;i++){
                cp16(sAu + (uint32_t)(nbuf*8192 + dstoff[i])*4u,        as + (af+i)*4);
                cp16(sAu + (uint32_t)(nbuf*8192 + 4096 + dstoff[i])*4u, bs + (af+i)*4);
            }
        }
        asm volatile("cp.async.commit_group;\n");

        const float* A  = smf + buf*8192;
        const float* Bs = smf + buf*8192 + 4096;
#pragma unroll
        for (int s=0;s<4;s++){
            const int c0 = s*8 + lc;
            uint32_t afr[4][4];
#pragma unroll
            for (int mi=0;mi<4;mi++){
                const int r = wm*64 + mi*16 + lr;
                afr[mi][0] = __float_as_uint(A[swzf(r,   c0)]);
                afr[mi][1] = __float_as_uint(A[swzf(r+8, c0)]);
                afr[mi][2] = __float_as_uint(A[swzf(r,   c0+4)]);
                afr[mi][3] = __float_as_uint(A[swzf(r+8, c0+4)]);
            }
            uint32_t bfr[4][2];
#pragma unroll
            for (int ni=0;ni<4;ni++){
                const int n = wn*32 + ni*8 + lr;
                bfr[ni][0] = cvt_tf32(Bs[swzf(n, c0)]);
                bfr[ni][1] = cvt_tf32(Bs[swzf(n, c0+4)]);
            }
#pragma unroll
            for (int mi=0;mi<4;mi++)
#pragma unroll
                for (int ni=0;ni<4;ni++)
                    mma_tf32(acc[mi][ni], afr[mi], bfr[ni]);
        }
        buf = (buf==2) ? 0 : buf+1;
        nbuf = (nbuf==2) ? 0 : nbuf+1;
    }

    float* Out = SILU ? g_hid : g_y;
#pragma unroll
    for (int mi=0;mi<4;mi++){
        const int rb = mtile*128 + wm*64 + mi*16 + lr;
#pragma unroll
        for (int ni=0;ni<4;ni++){
            const int nb = ntile*128 + wn*32 + ni*8 + lc*2;
            const float b0 = bias_e[nb], b1v = bias_e[nb+1];
#pragma unroll
            for (int h=0; h<2; h++){
                const int p = rb + h*8;
                float v0 = acc[mi][ni][h*2+0] + b0;
                float v1 = acc[mi][ni][h*2+1] + b1v;
                if (SILU){
                    v0 = v0 / (1.0f + expf(-v0));
                    v1 = v1 / (1.0f + expf(-v1));
                    v0 = __uint_as_float(cvt_tf32(v0));
                    v1 = __uint_as_float(cvt_tf32(v1));
                }
                *(float2*)(Out + (size_t)p*ND + nb) = make_float2(v0, v1);
            }
        }
    }
}

// warp per (b,d) row — coalesced float2 residual add
__global__ void resid_k(const float* __restrict__ x, float* __restrict__ out){
    int g = blockIdx.x*blockDim.x + threadIdx.x;
    int row = g >> 5, lane = g & 31;
    int b = row >> 10, d = row & 1023;
    float f = 0.f;
    if (lane == 0){
        f = g_topw[2*b]   * g_y[(size_t)g_slot[2*b]  *DIM + d]
          + g_topw[2*b+1] * g_y[(size_t)g_slot[2*b+1]*DIM + d];
    }
    f = __shfl_sync(0xffffffffu, f, 0);
    float2 v = ((const float2*)(x + (size_t)row*64))[lane];
    v.x += f; v.y += f;
    ((float2*)(out + (size_t)row*64))[lane] = v;
}

// ---------------- launch ----------------
extern "C" void kernel_launch(void* const* d_in, const int* in_sizes, int n_in,
                              void* d_out, int out_size){
    const float* x     = (const float*)d_in[0];
    const float* gamma = (const float*)d_in[1];
    const float* beta  = (const float*)d_in[2];
    const float* wg    = (const float*)d_in[3];
    const float* bg    = (const float*)d_in[4];
    const float* w1    = (const float*)d_in[5];
    const float* b1    = (const float*)d_in[6];
    const float* w2    = (const float*)d_in[7];
    const float* b2    = (const float*)d_in[8];
    float* out = (float*)d_out;

    cudaFuncSetAttribute(gemm_k<DIM, HID, true,  true >, cudaFuncAttributeMaxDynamicSharedMemorySize, 98304);
    cudaFuncSetAttribute(gemm_k<HID, DIM, false, false>, cudaFuncAttributeMaxDynamicSharedMemorySize, 98304);

    init_k<<<(CAP+255)/256, 256>>>();
    pool_k<<<(BTOK*DIM*32)/256, 256>>>(x);
    lngate_k<<<BTOK, 256>>>(gamma, beta, wg, bg);
    scan_k<<<1, 32>>>();
    scatter_k<<<(NSLOT+255)/256, 256>>>();
    gemm_k<DIM, HID, true,  true ><<<dim3(HID/128, MTILES), 256, 98304>>>(w1, b1);
    gemm_k<HID, DIM, false, false><<<dim3(DIM/128, MTILES), 256, 98304>>>(w2, b2);
    resid_k<<<(BTOK*DIM*32)/256, 256>>>(x, out);
}

// round 4
// speedup vs baseline: 1.2031x; 1.2031x over previous
#include <cuda_runtime.h>
#include <cstdint>
#include <math.h>

#define BTOK 4096
#define DIM 1024
#define HID 4096
#define NE 8
#define NSLOT (BTOK*2)
#define CAP 9216
#define MTILES (CAP/128)      // 72

// ---------------- scratch (device globals; no runtime allocation) ----------------
__device__ __align__(128) float g_xn[BTOK*DIM];            // pooled -> layernormed (tf32 RNA)
__device__ __align__(128) float g_hid[(size_t)CAP*HID];    // silu(hidden), tf32 RNA
__device__ __align__(128) float g_y[(size_t)CAP*DIM];      // expert outputs
__device__ int   g_tok[CAP];
__device__ int   g_slot[NSLOT];
__device__ float g_topw[NSLOT];
__device__ int   g_topi[NSLOT];
__device__ int   g_cnt[NE];
__device__ int   g_cur[NE];
__device__ int   g_off[NE+1];
__device__ int   g_tile_e[MTILES];

// ---------------- helpers ----------------
__device__ __forceinline__ uint32_t cvt_tf32(float x){
    uint32_t u; asm("cvt.rna.tf32.f32 %0, %1;" : "=r"(u) : "f"(x)); return u;
}
__device__ __forceinline__ void cp16(uint32_t dst, const void* src){
    asm volatile("cp.async.cg.shared.global [%0], [%1], 16;\n" :: "r"(dst), "l"(src));
}
__device__ __forceinline__ void mma_tf32(float* c, const uint32_t* a, const uint32_t* b){
    asm volatile("mma.sync.aligned.m16n8k8.row.col.f32.tf32.tf32.f32 "
        "{%0,%1,%2,%3}, {%4,%5,%6,%7}, {%8,%9}, {%0,%1,%2,%3};"
        : "+f"(c[0]), "+f"(c[1]), "+f"(c[2]), "+f"(c[3])
        : "r"(a[0]), "r"(a[1]), "r"(a[2]), "r"(a[3]), "r"(b[0]), "r"(b[1]));
}
// swizzled float index inside a [row][32-float] smem tile: conflict-free for mma frag reads
__device__ __forceinline__ int swzf(int r, int c){
    return r*32 + ((((c>>2) ^ (r & 7)) << 2) | (c & 3));
}

// ---------------- small kernels ----------------
__global__ void init_k(){
    int t = blockIdx.x*blockDim.x + threadIdx.x;
    if (t < NE){ g_cnt[t]=0; g_cur[t]=0; }
    if (t < MTILES) g_tile_e[t] = -1;
    if (t < CAP) g_tok[t] = 0;
}

// warp per (b,d) row of 64 spatial floats — coalesced float2 lane loads
__global__ void pool_k(const float* __restrict__ x){
    int g = blockIdx.x*blockDim.x + threadIdx.x;
    int row = g >> 5, lane = g & 31;
    float2 v = ((const float2*)(x + (size_t)row*64))[lane];
    float s = v.x + v.y;
#pragma unroll
    for (int o=16;o;o>>=1) s += __shfl_xor_sync(0xffffffffu, s, o);
    if (!lane) g_xn[row] = s * (1.0f/64.0f);
}

__global__ void __launch_bounds__(256) lngate_k(const float* __restrict__ gamma,
                                                const float* __restrict__ beta,
                                                const float* __restrict__ wg,
                                                const float* __restrict__ bg){
    const int b = blockIdx.x, t = threadIdx.x;
    __shared__ float srow[DIM];
    __shared__ float rs[8], rss[8], slog[8];
    float4 v = ((const float4*)(g_xn + (size_t)b*DIM))[t];
    float s  = (v.x+v.y)+(v.z+v.w);
    float ss = (v.x*v.x+v.y*v.y)+(v.z*v.z+v.w*v.w);
#pragma unroll
    for (int o=16;o;o>>=1){ s += __shfl_xor_sync(0xffffffffu, s, o); ss += __shfl_xor_sync(0xffffffffu, ss, o); }
    const int lane = t & 31, w = t >> 5;
    if (!lane){ rs[w]=s; rss[w]=ss; }
    __syncthreads();
    float tot=0.f, tot2=0.f;
#pragma unroll
    for (int i=0;i<8;i++){ tot += rs[i]; tot2 += rss[i]; }
    const float mean = tot * (1.0f/DIM);
    const float var  = tot2 * (1.0f/DIM) - mean*mean;
    const float rinv = rsqrtf(var + 1e-5f);
    float4 g4 = ((const float4*)gamma)[t];
    float4 be4 = ((const float4*)beta)[t];
    float4 xn;
    xn.x = (v.x-mean)*rinv*g4.x + be4.x;
    xn.y = (v.y-mean)*rinv*g4.y + be4.y;
    xn.z = (v.z-mean)*rinv*g4.z + be4.z;
    xn.w = (v.w-mean)*rinv*g4.w + be4.w;
    ((float4*)srow)[t] = xn;                 // full precision for gating
    float4 xr;
    xr.x = __uint_as_float(cvt_tf32(xn.x));
    xr.y = __uint_as_float(cvt_tf32(xn.y));
    xr.z = __uint_as_float(cvt_tf32(xn.z));
    xr.w = __uint_as_float(cvt_tf32(xn.w));
    ((float4*)(g_xn + (size_t)b*DIM))[t] = xr;   // tf32-rounded for GEMM
    __syncthreads();
    const float4* wrow = (const float4*)(wg + (size_t)w*DIM);
    const float4* sr = (const float4*)srow;
    float acc = 0.f;
#pragma unroll
    for (int i=0;i<8;i++){
        int idx = lane + i*32;
        float4 a = sr[idx], ww = wrow[idx];
        acc += a.x*ww.x + a.y*ww.y + a.z*ww.z + a.w*ww.w;
    }
#pragma unroll
    for (int o=16;o;o>>=1) acc += __shfl_xor_sync(0xffffffffu, acc, o);
    if (!lane) slog[w] = acc + bg[w];
    __syncthreads();
    if (!t){
        int e0 = 0;
#pragma unroll
        for (int i=1;i<8;i++) if (slog[i] > slog[e0]) e0 = i;
        int e1 = (e0==0) ? 1 : 0;
#pragma unroll
        for (int i=0;i<8;i++) if (i!=e0 && slog[i] > slog[e1]) e1 = i;
        float z = expf(slog[e1] - slog[e0]);      // v1 <= v0
        g_topi[b*2]=e0; g_topi[b*2+1]=e1;
        g_topw[b*2]=1.0f/(1.0f+z); g_topw[b*2+1]=z/(1.0f+z);
        atomicAdd(&g_cnt[e0],1); atomicAdd(&g_cnt[e1],1);
    }
}

__global__ void scan_k(){
    if (threadIdx.x==0 && blockIdx.x==0){
        int off = 0;
        for (int e=0;e<NE;e++){
            g_off[e] = off;
            int nt = (g_cnt[e] + 127) >> 7;
            int t0 = off >> 7;
            for (int i=0;i<nt;i++) g_tile_e[t0+i] = e;
            off += nt << 7;
        }
        g_off[NE] = off;
    }
}

__global__ void scatter_k(){
    int i = blockIdx.x*blockDim.x + threadIdx.x;
    if (i >= NSLOT) return;
    int e = g_topi[i];
    int p = g_off[e] + atomicAdd(&g_cur[e], 1);
    g_tok[p] = i >> 1;
    g_slot[i] = p;
}

// ---------------- 4-stage pipelined tf32 mma GEMM ----------------
// C[mtile*128+m, ntile*128+n] = A[m,:] . W[e, n, :]   (both K-major)
// smem: 4 stages x (A 128x32 + B 128x32 floats) = 4 x 32KB = 128KB; 1 CTA/SM, no reg cap
template<int KD, int ND, bool GATHER, bool SILU>
__global__ void __launch_bounds__(256) gemm_k(const float* __restrict__ W,
                                              const float* __restrict__ bias){
    extern __shared__ float smf[];
    const int ntile = blockIdx.x, mtile = blockIdx.y;
    const int e = g_tile_e[mtile];
    if (e < 0) return;
    const int t = threadIdx.x;
    const int arow = t >> 1;           // 0..127
    const int af   = (t & 1) * 4;      // float4 slot base within 32-float chunk

    const float* aptr;
    if (GATHER) aptr = g_xn  + (size_t)g_tok[mtile*128 + arow]*KD;
    else        aptr = g_hid + (size_t)(mtile*128 + arow)*KD;
    const float* bptr = W + (size_t)e*ND*KD + (size_t)(ntile*128 + arow)*KD;
    const float* bias_e = bias + (size_t)e*ND;

    uint32_t sAu = (uint32_t)__cvta_generic_to_shared(smf);
    int dstoff[4];
#pragma unroll
    for (int i=0;i<4;i++){
        int f = af + i;
        dstoff[i] = arow*32 + ((f ^ (arow & 7)) << 2);   // floats
    }

    const int NK = KD/32;
    // prologue: stages 0..2
#pragma unroll
    for (int c=0;c<3;c++){
#pragma unroll
        for (int i=0;i<4;i++){
            cp16(sAu + (uint32_t)(c*8192 + dstoff[i])*4u,        aptr + c*32 + (af+i)*4);
            cp16(sAu + (uint32_t)(c*8192 + 4096 + dstoff[i])*4u, bptr + c*32 + (af+i)*4);
        }
        asm volatile("cp.async.commit_group;\n");
    }

    const int w = t>>5, lane = t&31;
    const int wm = w & 1, wn = w >> 1;        // 2 x 4 warp grid; warp tile 64x32
    const int lr = lane >> 2, lc = lane & 3;
    float acc[4][4][4];
#pragma unroll
    for (int a=0;a<4;a++)
#pragma unroll
        for (int bb=0;bb<4;bb++)
#pragma unroll
            for (int c=0;c<4;c++) acc[a][bb][c] = 0.f;

    for (int kc=0; kc<NK; kc++){
        const int buf = kc & 3;
        asm volatile("cp.async.wait_group 2;\n");     // stage kc resident; 2 still in flight
        __syncthreads();
        // prefetch stage kc+3 into buffer (kc+3)&3 == (kc-1)&3 (compute done last iter,
        // all warps past it due to the sync above)
        if (kc+3 < NK){
            const int nb = (kc+3) & 3;
            const float* as = aptr + (kc+3)*32;
            const float* bs = bptr + (kc+3)*32;
#pragma unroll
            for (int i=0;i<4;i++){
                cp16(sAu + (uint32_t)(nb*8192 + dstoff[i])*4u,        as + (af+i)*4);
                cp16(sAu + (uint32_t)(nb*8192 + 4096 + dstoff[i])*4u, bs + (af+i)*4);
            }
        }
        asm volatile("cp.async.commit_group;\n");

        const float* A  = smf + buf*8192;
        const float* Bs = smf + buf*8192 + 4096;
#pragma unroll
        for (int s=0;s<4;s++){
            const int c0 = s*8 + lc;
            uint32_t afr[4][4];
#pragma unroll
            for (int mi=0;mi<4;mi++){
                const int r = wm*64 + mi*16 + lr;
                afr[mi][0] = __float_as_uint(A[swzf(r,   c0)]);
                afr[mi][1] = __float_as_uint(A[swzf(r+8, c0)]);
                afr[mi][2] = __float_as_uint(A[swzf(r,   c0+4)]);
                afr[mi][3] = __float_as_uint(A[swzf(r+8, c0+4)]);
            }
            uint32_t bfr[4][2];
#pragma unroll
            for (int ni=0;ni<4;ni++){
                const int n = wn*32 + ni*8 + lr;
                bfr[ni][0] = cvt_tf32(Bs[swzf(n, c0)]);
                bfr[ni][1] = cvt_tf32(Bs[swzf(n, c0+4)]);
            }
#pragma unroll
            for (int mi=0;mi<4;mi++)
#pragma unroll
                for (int ni=0;ni<4;ni++)
                    mma_tf32(acc[mi][ni], afr[mi], bfr[ni]);
        }
    }

    float* Out = SILU ? g_hid : g_y;
#pragma unroll
    for (int mi=0;mi<4;mi++){
        const int rb = mtile*128 + wm*64 + mi*16 + lr;
#pragma unroll
        for (int ni=0;ni<4;ni++){
            const int nb = ntile*128 + wn*32 + ni*8 + lc*2;
            const float b0 = bias_e[nb], b1v = bias_e[nb+1];
#pragma unroll
            for (int h=0; h<2; h++){
                const int p = rb + h*8;
                float v0 = acc[mi][ni][h*2+0] + b0;
                float v1 = acc[mi][ni][h*2+1] + b1v;
                if (SILU){
                    v0 = v0 / (1.0f + expf(-v0));
                    v1 = v1 / (1.0f + expf(-v1));
                    v0 = __uint_as_float(cvt_tf32(v0));
                    v1 = __uint_as_float(cvt_tf32(v1));
                }
                *(float2*)(Out + (size_t)p*ND + nb) = make_float2(v0, v1);
            }
        }
    }
}

// warp per (b,d) row — coalesced float2 residual add
__global__ void resid_k(const float* __restrict__ x, float* __restrict__ out){
    int g = blockIdx.x*blockDim.x + threadIdx.x;
    int row = g >> 5, lane = g & 31;
    int b = row >> 10, d = row & 1023;
    float f = 0.f;
    if (lane == 0){
        f = g_topw[2*b]   * g_y[(size_t)g_slot[2*b]  *DIM + d]
          + g_topw[2*b+1] * g_y[(size_t)g_slot[2*b+1]*DIM + d];
    }
    f = __shfl_sync(0xffffffffu, f, 0);
    float2 v = ((const float2*)(x + (size_t)row*64))[lane];
    v.x += f; v.y += f;
    ((float2*)(out + (size_t)row*64))[lane] = v;
}

// ---------------- launch ----------------
extern "C" void kernel_launch(void* const* d_in, const int* in_sizes, int n_in,
                              void* d_out, int out_size){
    const float* x     = (const float*)d_in[0];
    const float* gamma = (const float*)d_in[1];
    const float* beta  = (const float*)d_in[2];
    const float* wg    = (const float*)d_in[3];
    const float* bg    = (const float*)d_in[4];
    const float* w1    = (const float*)d_in[5];
    const float* b1    = (const float*)d_in[6];
    const float* w2    = (const float*)d_in[7];
    const float* b2    = (const float*)d_in[8];
    float* out = (float*)d_out;

    cudaFuncSetAttribute(gemm_k<DIM, HID, true,  true >, cudaFuncAttributeMaxDynamicSharedMemorySize, 131072);
    cudaFuncSetAttribute(gemm_k<HID, DIM, false, false>, cudaFuncAttributeMaxDynamicSharedMemorySize, 131072);

    init_k<<<(CAP+255)/256, 256>>>();
    pool_k<<<(BTOK*DIM*32)/256, 256>>>(x);
    lngate_k<<<BTOK, 256>>>(gamma, beta, wg, bg);
    scan_k<<<1, 32>>>();
    scatter_k<<<(NSLOT+255)/256, 256>>>();
    gemm_k<DIM, HID, true,  true ><<<dim3(HID/128, MTILES), 256, 131072>>>(w1, b1);
    gemm_k<HID, DIM, false, false><<<dim3(DIM/128, MTILES), 256, 131072>>>(w2, b2);
    resid_k<<<(BTOK*DIM*32)/256, 256>>>(x, out);
}

// round 5
// speedup vs baseline: 1.4177x; 1.1784x over previous
#include <cuda_runtime.h>
#include <cstdint>
#include <math.h>

#define BTOK 4096
#define DIM 1024
#define HID 4096
#define NE 8
#define NSLOT (BTOK*2)
#define CAP 9216
#define MTILES (CAP/128)      // 72

// ---------------- scratch (device globals; no runtime allocation) ----------------
__device__ __align__(128) float g_xn[BTOK*DIM];            // pooled -> layernormed (tf32 RNA)
__device__ __align__(128) float g_hid[(size_t)CAP*HID];    // silu(hidden), tf32 RNA
__device__ __align__(128) float g_y[(size_t)CAP*DIM];      // expert outputs
__device__ int   g_tok[CAP];
__device__ int   g_slot[NSLOT];
__device__ float g_topw[NSLOT];
__device__ int   g_topi[NSLOT];
__device__ int   g_cnt[NE];
__device__ int   g_off[NE+1];
__device__ int   g_tile_e[MTILES];

// ---------------- helpers ----------------
__device__ __forceinline__ uint32_t cvt_tf32(float x){
    uint32_t u; asm("cvt.rna.tf32.f32 %0, %1;" : "=r"(u) : "f"(x)); return u;
}
__device__ __forceinline__ void cp16(uint32_t dst, const void* src){
    asm volatile("cp.async.cg.shared.global [%0], [%1], 16;\n" :: "r"(dst), "l"(src));
}
__device__ __forceinline__ void mma_tf32(float* c, const uint32_t* a, const uint32_t* b){
    asm volatile("mma.sync.aligned.m16n8k8.row.col.f32.tf32.tf32.f32 "
        "{%0,%1,%2,%3}, {%4,%5,%6,%7}, {%8,%9}, {%0,%1,%2,%3};"
        : "+f"(c[0]), "+f"(c[1]), "+f"(c[2]), "+f"(c[3])
        : "r"(a[0]), "r"(a[1]), "r"(a[2]), "r"(a[3]), "r"(b[0]), "r"(b[1]));
}
// swizzled float index inside a [row][32-float] smem tile
__device__ __forceinline__ int swzf(int r, int c){
    return r*32 + ((((c>>2) ^ (r & 7)) << 2) | (c & 3));
}

// ---------------- fused init + pool: warp per (b,d) row ----------------
__global__ void pool_k(const float* __restrict__ x){
    if (blockIdx.x == 0){
        int t = threadIdx.x;
        if (t < NE) g_cnt[t] = 0;
        if (t < MTILES) g_tile_e[t] = -1;
        for (int i = t; i < CAP; i += 256) g_tok[i] = 0;
    }
    int g = blockIdx.x*blockDim.x + threadIdx.x;
    int row = g >> 5, lane = g & 31;
    float2 v = ((const float2*)(x + (size_t)row*64))[lane];
    float s = v.x + v.y;
#pragma unroll
    for (int o=16;o;o>>=1) s += __shfl_xor_sync(0xffffffffu, s, o);
    if (!lane) g_xn[row] = s * (1.0f/64.0f);
}

__global__ void __launch_bounds__(256) lngate_k(const float* __restrict__ gamma,
                                                const float* __restrict__ beta,
                                                const float* __restrict__ wg,
                                                const float* __restrict__ bg){
    const int b = blockIdx.x, t = threadIdx.x;
    __shared__ float srow[DIM];
    __shared__ float rs[8], rss[8], slog[8];
    float4 v = ((const float4*)(g_xn + (size_t)b*DIM))[t];
    float s  = (v.x+v.y)+(v.z+v.w);
    float ss = (v.x*v.x+v.y*v.y)+(v.z*v.z+v.w*v.w);
#pragma unroll
    for (int o=16;o;o>>=1){ s += __shfl_xor_sync(0xffffffffu, s, o); ss += __shfl_xor_sync(0xffffffffu, ss, o); }
    const int lane = t & 31, w = t >> 5;
    if (!lane){ rs[w]=s; rss[w]=ss; }
    __syncthreads();
    float tot=0.f, tot2=0.f;
#pragma unroll
    for (int i=0;i<8;i++){ tot += rs[i]; tot2 += rss[i]; }
    const float mean = tot * (1.0f/DIM);
    const float var  = tot2 * (1.0f/DIM) - mean*mean;
    const float rinv = rsqrtf(var + 1e-5f);
    float4 g4 = ((const float4*)gamma)[t];
    float4 be4 = ((const float4*)beta)[t];
    float4 xn;
    xn.x = (v.x-mean)*rinv*g4.x + be4.x;
    xn.y = (v.y-mean)*rinv*g4.y + be4.y;
    xn.z = (v.z-mean)*rinv*g4.z + be4.z;
    xn.w = (v.w-mean)*rinv*g4.w + be4.w;
    ((float4*)srow)[t] = xn;                 // full precision for gating
    float4 xr;
    xr.x = __uint_as_float(cvt_tf32(xn.x));
    xr.y = __uint_as_float(cvt_tf32(xn.y));
    xr.z = __uint_as_float(cvt_tf32(xn.z));
    xr.w = __uint_as_float(cvt_tf32(xn.w));
    ((float4*)(g_xn + (size_t)b*DIM))[t] = xr;   // tf32-rounded for GEMM
    __syncthreads();
    const float4* wrow = (const float4*)(wg + (size_t)w*DIM);
    const float4* sr = (const float4*)srow;
    float acc = 0.f;
#pragma unroll
    for (int i=0;i<8;i++){
        int idx = lane + i*32;
        float4 a = sr[idx], ww = wrow[idx];
        acc += a.x*ww.x + a.y*ww.y + a.z*ww.z + a.w*ww.w;
    }
#pragma unroll
    for (int o=16;o;o>>=1) acc += __shfl_xor_sync(0xffffffffu, acc, o);
    if (!lane) slog[w] = acc + bg[w];
    __syncthreads();
    if (!t){
        int e0 = 0;
#pragma unroll
        for (int i=1;i<8;i++) if (slog[i] > slog[e0]) e0 = i;
        int e1 = (e0==0) ? 1 : 0;
#pragma unroll
        for (int i=0;i<8;i++) if (i!=e0 && slog[i] > slog[e1]) e1 = i;
        float z = expf(slog[e1] - slog[e0]);      // v1 <= v0
        g_topi[b*2]=e0; g_topi[b*2+1]=e1;
        g_topw[b*2]=1.0f/(1.0f+z); g_topw[b*2+1]=z/(1.0f+z);
        atomicAdd(&g_cnt[e0],1); atomicAdd(&g_cnt[e1],1);
    }
}

// fused scan + scatter: single block, smem counters
__global__ void __launch_bounds__(256) scanscatter_k(){
    __shared__ int cur[NE];
    const int t = threadIdx.x;
    if (t == 0){
        int off = 0;
        for (int e=0;e<NE;e++){
            g_off[e] = off;
            int nt = (g_cnt[e] + 127) >> 7;
            int t0 = off >> 7;
            for (int i=0;i<nt;i++) g_tile_e[t0+i] = e;
            off += nt << 7;
        }
        g_off[NE] = off;
    }
    if (t < NE) cur[t] = 0;
    __syncthreads();
    for (int i=t; i<NSLOT; i+=256){
        int e = g_topi[i];
        int p = g_off[e] + atomicAdd(&cur[e], 1);
        g_tok[p] = i >> 1;
        g_slot[i] = p;
    }
}

// ---------------- tf32 mma GEMM: CTA tile 128x256, warp tile 64x64 ----------------
// C[mtile*128+m, ntile*256+n] = A[m,:] . W[e, n, :]   (both K-major)
// smem: 4 stages x (A 128x32 + B 256x32 floats) = 4 x 48KB = 192KB; 1 CTA/SM
template<int KD, int ND, bool GATHER, bool SILU>
__global__ void __launch_bounds__(256) gemm_k(const float* __restrict__ W,
                                              const float* __restrict__ bias){
    extern __shared__ float smf[];
    const int ntile = blockIdx.x, mtile = blockIdx.y;
    const int e = g_tile_e[mtile];
    if (e < 0) return;
    const int t = threadIdx.x;

    // ---- loader setup: A 4 rows/thread-chunk, B 8 ----
    const float* aptr[4]; int aoff[4];
    const float* bptr[8]; int boff[8];
#pragma unroll
    for (int i=0;i<4;i++){
        int idx = t + i*256;            // 0..1023
        int r = idx >> 3, f = idx & 7;
        aoff[i] = r*32 + ((f ^ (r&7)) << 2);
        const float* base;
        if (GATHER) base = g_xn  + (size_t)g_tok[mtile*128 + r]*KD;
        else        base = g_hid + (size_t)(mtile*128 + r)*KD;
        aptr[i] = base + f*4;
    }
#pragma unroll
    for (int i=0;i<8;i++){
        int idx = t + i*256;            // 0..2047
        int r = idx >> 3, f = idx & 7;
        boff[i] = r*32 + ((f ^ (r&7)) << 2);
        bptr[i] = W + (size_t)e*ND*KD + (size_t)(ntile*256 + r)*KD + f*4;
    }
    const float* bias_e = bias + (size_t)e*ND;
    uint32_t sAu = (uint32_t)__cvta_generic_to_shared(smf);

    const int NK = KD/32;
    // prologue: stages 0..2   (stage stride 12288 floats: A 4096 + B 8192)
#pragma unroll
    for (int c=0;c<3;c++){
#pragma unroll
        for (int i=0;i<4;i++) cp16(sAu + (uint32_t)(c*12288 + aoff[i])*4u,        aptr[i] + c*32);
#pragma unroll
        for (int i=0;i<8;i++) cp16(sAu + (uint32_t)(c*12288 + 4096 + boff[i])*4u, bptr[i] + c*32);
        asm volatile("cp.async.commit_group;\n");
    }

    const int w = t>>5, lane = t&31;
    const int wm = w & 1, wn = w >> 1;        // 2 x 4 warp grid; warp tile 64x64
    const int lr = lane >> 2, lc = lane & 3;
    float acc[4][8][4];
#pragma unroll
    for (int a=0;a<4;a++)
#pragma unroll
        for (int bb=0;bb<8;bb++)
#pragma unroll
            for (int c=0;c<4;c++) acc[a][bb][c] = 0.f;

    for (int kc=0; kc<NK; kc++){
        const int buf = kc & 3;
        asm volatile("cp.async.wait_group 2;\n");
        __syncthreads();
        if (kc+3 < NK){
            const int nb = (kc+3) & 3;
#pragma unroll
            for (int i=0;i<4;i++) cp16(sAu + (uint32_t)(nb*12288 + aoff[i])*4u,        aptr[i] + (kc+3)*32);
#pragma unroll
            for (int i=0;i<8;i++) cp16(sAu + (uint32_t)(nb*12288 + 4096 + boff[i])*4u, bptr[i] + (kc+3)*32);
        }
        asm volatile("cp.async.commit_group;\n");

        const float* A  = smf + buf*12288;
        const float* Bs = smf + buf*12288 + 4096;
#pragma unroll
        for (int s=0;s<4;s++){
            const int c0 = s*8 + lc;
            uint32_t afr[4][4];
#pragma unroll
            for (int mi=0;mi<4;mi++){
                const int r = wm*64 + mi*16 + lr;
                afr[mi][0] = __float_as_uint(A[swzf(r,   c0)]);
                afr[mi][1] = __float_as_uint(A[swzf(r+8, c0)]);
                afr[mi][2] = __float_as_uint(A[swzf(r,   c0+4)]);
                afr[mi][3] = __float_as_uint(A[swzf(r+8, c0+4)]);
            }
            uint32_t bfr[8][2];
#pragma unroll
            for (int ni=0;ni<8;ni++){
                const int n = wn*64 + ni*8 + lr;
                bfr[ni][0] = cvt_tf32(Bs[swzf(n, c0)]);
                bfr[ni][1] = cvt_tf32(Bs[swzf(n, c0+4)]);
            }
#pragma unroll
            for (int mi=0;mi<4;mi++)
#pragma unroll
                for (int ni=0;ni<8;ni++)
                    mma_tf32(acc[mi][ni], afr[mi], bfr[ni]);
        }
    }

    float* Out = SILU ? g_hid : g_y;
#pragma unroll
    for (int mi=0;mi<4;mi++){
        const int rb = mtile*128 + wm*64 + mi*16 + lr;
#pragma unroll
        for (int ni=0;ni<8;ni++){
            const int nb = ntile*256 + wn*64 + ni*8 + lc*2;
            const float b0 = bias_e[nb], b1v = bias_e[nb+1];
#pragma unroll
            for (int h=0; h<2; h++){
                const int p = rb + h*8;
                float v0 = acc[mi][ni][h*2+0] + b0;
                float v1 = acc[mi][ni][h*2+1] + b1v;
                if (SILU){
                    v0 = v0 / (1.0f + expf(-v0));
                    v1 = v1 / (1.0f + expf(-v1));
                    v0 = __uint_as_float(cvt_tf32(v0));
                    v1 = __uint_as_float(cvt_tf32(v1));
                }
                *(float2*)(Out + (size_t)p*ND + nb) = make_float2(v0, v1);
            }
        }
    }
}

// warp per (b,d) row — coalesced float2 residual add
__global__ void resid_k(const float* __restrict__ x, float* __restrict__ out){
    int g = blockIdx.x*blockDim.x + threadIdx.x;
    int row = g >> 5, lane = g & 31;
    int b = row >> 10, d = row & 1023;
    float f = 0.f;
    if (lane == 0){
        f = g_topw[2*b]   * g_y[(size_t)g_slot[2*b]  *DIM + d]
          + g_topw[2*b+1] * g_y[(size_t)g_slot[2*b+1]*DIM + d];
    }
    f = __shfl_sync(0xffffffffu, f, 0);
    float2 v = ((const float2*)(x + (size_t)row*64))[lane];
    v.x += f; v.y += f;
    ((float2*)(out + (size_t)row*64))[lane] = v;
}

// ---------------- launch ----------------
extern "C" void kernel_launch(void* const* d_in, const int* in_sizes, int n_in,
                              void* d_out, int out_size){
    const float* x     = (const float*)d_in[0];
    const float* gamma = (const float*)d_in[1];
    const float* beta  = (const float*)d_in[2];
    const float* wg    = (const float*)d_in[3];
    const float* bg    = (const float*)d_in[4];
    const float* w1    = (const float*)d_in[5];
    const float* b1    = (const float*)d_in[6];
    const float* w2    = (const float*)d_in[7];
    const float* b2    = (const float*)d_in[8];
    float* out = (float*)d_out;

    cudaFuncSetAttribute(gemm_k<DIM, HID, true,  true >, cudaFuncAttributeMaxDynamicSharedMemorySize, 196608);
    cudaFuncSetAttribute(gemm_k<HID, DIM, false, false>, cudaFuncAttributeMaxDynamicSharedMemorySize, 196608);

    pool_k<<<(BTOK*DIM*32)/256, 256>>>(x);            // fused init
    lngate_k<<<BTOK, 256>>>(gamma, beta, wg, bg);
    scanscatter_k<<<1, 256>>>();
    gemm_k<DIM, HID, true,  true ><<<dim3(HID/256, MTILES), 256, 196608>>>(w1, b1);   // 4th launch -> ncu
    gemm_k<HID, DIM, false, false><<<dim3(DIM/256, MTILES), 256, 196608>>>(w2, b2);
    resid_k<<<(BTOK*DIM*32)/256, 256>>>(x, out);
}